// round 1
// baseline (speedup 1.0000x reference)
#include <cuda_runtime.h>
#include <math.h>

// ---------------- problem constants ----------------
#define NNODES 5461          // (4^7-1)/3
#define LEAF_START 1365
#define NLEAF 4096
#define DIM 512

typedef unsigned long long ull;

// ---------------- scratch (__device__ globals; no allocation allowed) ----------------
__device__ float g_ioux_v[NNODES * 1536];
__device__ float g_ioux_l[NNODES * 1536];
__device__ float g_fx_v[NNODES * DIM];
__device__ float g_fx_l[NNODES * DIM];
__device__ float g_c[NNODES * DIM];
__device__ float g_hsum[1024 * DIM];
__device__ float g_hsiou_v[1024 * 1536];
__device__ float g_hsiou_l[1024 * 1536];
__device__ float g_fh_v[4096 * DIM];
__device__ float g_fh_l[4096 * DIM];
__device__ int   g_sel[NNODES];

// ---------------- packed f32x2 helpers (Blackwell FFMA2) ----------------
__device__ __forceinline__ ull f2_pack(float lo, float hi) {
    ull r;
    asm("mov.b64 %0, {%1, %2};" : "=l"(r) : "f"(lo), "f"(hi));
    return r;
}
__device__ __forceinline__ void f2_fma(ull& d, ull a, ull b) {
    asm("fma.rn.f32x2 %0, %1, %2, %3;" : "=l"(d) : "l"(a), "l"(b), "l"(d));
}
__device__ __forceinline__ float2 f2_unpack(ull v) {
    float2 f;
    asm("mov.b64 {%0, %1}, %2;" : "=f"(f.x), "=f"(f.y) : "l"(v));
    return f;
}

__device__ __forceinline__ float sigmf(float x) { return 1.0f / (1.0f + expf(-x)); }

// ---------------- generic GEMM: C[M,Nc] = A[M,512] @ B[512,Nc] (+bias) ----------------
// BM=64, BN=128, BK=8, 256 threads, 4x8 micro-tile per thread, FFMA2 inner loop.
// Requires: Nc % 128 == 0 (true for 512/1024/1536). M handled with predicates.
__global__ void __launch_bounds__(256) gemm512(
    const float* __restrict__ A, const float* __restrict__ B,
    const float* __restrict__ bias, float* __restrict__ C,
    int M, int Nc)
{
    __shared__ __align__(16) float As[8][64];
    __shared__ __align__(16) float Bs[8][128];

    const int tid  = threadIdx.x;
    const int row0 = blockIdx.y * 64;
    const int col0 = blockIdx.x * 128;
    const int tx   = tid & 15;       // 16 col-groups of 8
    const int ty   = tid >> 4;       // 16 row-groups of 4

    // global-load mapping
    const int arow = tid >> 2;              // 0..63
    const int acol = (tid & 3) * 2;         // 0,2,4,6  (float2)
    const int brow = tid >> 5;              // 0..7
    const int bcol = (tid & 31) * 4;        // 0..124   (float4)

    ull acc[4][4];
#pragma unroll
    for (int i = 0; i < 4; i++)
#pragma unroll
        for (int j = 0; j < 4; j++) acc[i][j] = 0ull;

    const bool a_ok = (row0 + arow) < M;
    const float* Aptr = A + (size_t)(row0 + arow) * DIM + acol;
    const float* Bptr = B + (size_t)brow * Nc + col0 + bcol;

    for (int k0 = 0; k0 < DIM; k0 += 8) {
        float2 av = make_float2(0.f, 0.f);
        if (a_ok) av = *(const float2*)(Aptr + k0);
        As[acol][arow]     = av.x;
        As[acol + 1][arow] = av.y;
        *(float4*)&Bs[brow][bcol] = *(const float4*)(Bptr + (size_t)k0 * Nc);
        __syncthreads();
#pragma unroll
        for (int kk = 0; kk < 8; kk++) {
            float4 a = *(const float4*)&As[kk][ty * 4];
            // b pairs load directly as packed 64-bit values (adjacent floats)
            ulonglong2 b01 = *(const ulonglong2*)&Bs[kk][tx * 8];
            ulonglong2 b23 = *(const ulonglong2*)&Bs[kk][tx * 8 + 4];
            ull a0 = f2_pack(a.x, a.x);
            ull a1 = f2_pack(a.y, a.y);
            ull a2 = f2_pack(a.z, a.z);
            ull a3 = f2_pack(a.w, a.w);
            f2_fma(acc[0][0], a0, b01.x); f2_fma(acc[0][1], a0, b01.y);
            f2_fma(acc[0][2], a0, b23.x); f2_fma(acc[0][3], a0, b23.y);
            f2_fma(acc[1][0], a1, b01.x); f2_fma(acc[1][1], a1, b01.y);
            f2_fma(acc[1][2], a1, b23.x); f2_fma(acc[1][3], a1, b23.y);
            f2_fma(acc[2][0], a2, b01.x); f2_fma(acc[2][1], a2, b01.y);
            f2_fma(acc[2][2], a2, b23.x); f2_fma(acc[2][3], a2, b23.y);
            f2_fma(acc[3][0], a3, b01.x); f2_fma(acc[3][1], a3, b01.y);
            f2_fma(acc[3][2], a3, b23.x); f2_fma(acc[3][3], a3, b23.y);
        }
        __syncthreads();
    }

    const int c = col0 + tx * 8;
#pragma unroll
    for (int i = 0; i < 4; i++) {
        int r = row0 + ty * 4 + i;
        if (r < M) {
            float2 v0 = f2_unpack(acc[i][0]);
            float2 v1 = f2_unpack(acc[i][1]);
            float2 v2 = f2_unpack(acc[i][2]);
            float2 v3 = f2_unpack(acc[i][3]);
            if (bias) {
                v0.x += bias[c + 0]; v0.y += bias[c + 1];
                v1.x += bias[c + 2]; v1.y += bias[c + 3];
                v2.x += bias[c + 4]; v2.y += bias[c + 5];
                v3.x += bias[c + 6]; v3.y += bias[c + 7];
            }
            float* Crow = C + (size_t)r * Nc + c;
            *(float4*)(Crow)     = make_float4(v0.x, v0.y, v1.x, v1.y);
            *(float4*)(Crow + 4) = make_float4(v2.x, v2.y, v3.x, v3.y);
        }
    }
}

// ---------------- modality selection: sel[n] = argmax(x[n] @ W_type + b_type) == 0 ----------------
__global__ void sel_kernel(const float* __restrict__ x,
                           const float* __restrict__ Wt,
                           const float* __restrict__ bt)
{
    int n = blockIdx.x * (blockDim.x >> 5) + (threadIdx.x >> 5);
    int lane = threadIdx.x & 31;
    if (n >= NNODES) return;
    float s0 = 0.f, s1 = 0.f;
    const float* xr = x + (size_t)n * DIM;
#pragma unroll 4
    for (int k = lane; k < DIM; k += 32) {
        float xv = xr[k];
        s0 = fmaf(xv, Wt[k * 2 + 0], s0);
        s1 = fmaf(xv, Wt[k * 2 + 1], s1);
    }
#pragma unroll
    for (int o = 16; o > 0; o >>= 1) {
        s0 += __shfl_xor_sync(0xFFFFFFFFu, s0, o);
        s1 += __shfl_xor_sync(0xFFFFFFFFu, s1, o);
    }
    if (lane == 0) g_sel[n] = (s0 + bt[0] >= s1 + bt[1]) ? 1 : 0;  // argmax==0 -> lang
}

// ---------------- leaf nodes: no children, pure elementwise on selected modality ----------------
__global__ void leaf_kernel(const float* __restrict__ b_iouh_v,
                            const float* __restrict__ b_iouh_l,
                            float* __restrict__ h_out)
{
    int idx = blockIdx.x * blockDim.x + threadIdx.x;
    if (idx >= NLEAF * DIM) return;
    int n = LEAF_START + (idx >> 9);
    int j = idx & (DIM - 1);
    int sl = g_sel[n];
    const float* ioux = sl ? g_ioux_l : g_ioux_v;
    const float* bi   = sl ? b_iouh_l : b_iouh_v;
    size_t base = (size_t)n * 1536;
    float ig = ioux[base + j]        + bi[j];
    float og = ioux[base + 512 + j]  + bi[512 + j];
    float ug = ioux[base + 1024 + j] + bi[1024 + j];
    float cc = sigmf(ig) * tanhf(ug);
    float hh = sigmf(og) * tanhf(cc);
    g_c[(size_t)n * DIM + j] = cc;
    h_out[(size_t)n * DIM + j] = hh;
}

// ---------------- h_sum: sum of 4 consecutive child rows ----------------
__global__ void hsum_kernel(const float* __restrict__ h_all, int S1, int E)
{
    int idx = blockIdx.x * blockDim.x + threadIdx.x;
    if (idx >= E * DIM) return;
    int i = idx >> 9, j = idx & (DIM - 1);
    const float* b = h_all + (size_t)(S1 + 4 * i) * DIM + j;
    g_hsum[idx] = (b[0] + b[DIM]) + (b[2 * DIM] + b[3 * DIM]);
}

// ---------------- internal-node gates (selected modality only) ----------------
__global__ void gates_kernel(int s, int S1, int E,
                             const float* __restrict__ b_iouh_v,
                             const float* __restrict__ b_iouh_l,
                             const float* __restrict__ b_fh_v,
                             const float* __restrict__ b_fh_l,
                             float* __restrict__ h_out)
{
    int idx = blockIdx.x * blockDim.x + threadIdx.x;
    if (idx >= E * DIM) return;
    int i = idx >> 9, j = idx & (DIM - 1);
    int n = s + i;
    int sl = g_sel[n];
    const float* ioux  = sl ? g_ioux_l  : g_ioux_v;
    const float* hsiou = sl ? g_hsiou_l : g_hsiou_v;
    const float* fh    = sl ? g_fh_l    : g_fh_v;
    const float* fx    = sl ? g_fx_l    : g_fx_v;
    const float* bi    = sl ? b_iouh_l  : b_iouh_v;
    const float* bf    = sl ? b_fh_l    : b_fh_v;

    size_t xb = (size_t)n * 1536;
    size_t hb = (size_t)i * 1536;
    float ig = ioux[xb + j]        + hsiou[hb + j]        + bi[j];
    float og = ioux[xb + 512 + j]  + hsiou[hb + 512 + j]  + bi[512 + j];
    float ug = ioux[xb + 1024 + j] + hsiou[hb + 1024 + j] + bi[1024 + j];
    float fxv = fx[(size_t)n * DIM + j] + bf[j];

    float cc = sigmf(ig) * tanhf(ug);
    size_t c0 = (size_t)(S1 + 4 * i) * DIM + j;
    size_t f0 = (size_t)(4 * i) * DIM + j;
#pragma unroll
    for (int k = 0; k < 4; k++) {
        float f = sigmf(fh[f0 + (size_t)k * DIM] + fxv);
        cc = fmaf(f, g_c[c0 + (size_t)k * DIM], cc);
    }
    float hh = sigmf(og) * tanhf(cc);
    g_c[(size_t)n * DIM + j] = cc;
    h_out[(size_t)n * DIM + j] = hh;
}

// ---------------- launch ----------------
extern "C" void kernel_launch(void* const* d_in, const int* in_sizes, int n_in,
                              void* d_out, int out_size)
{
    const float* x        = (const float*)d_in[0];
    // d_in[1] = children (structure is implicit: child(n,k) = 4n+1+k)
    const float* W_ioux_v = (const float*)d_in[2];
    const float* b_ioux_v = (const float*)d_in[3];
    const float* W_iouh_v = (const float*)d_in[4];
    const float* b_iouh_v = (const float*)d_in[5];
    const float* W_fx_v   = (const float*)d_in[6];
    const float* b_fx_v   = (const float*)d_in[7];
    const float* W_fh_v   = (const float*)d_in[8];
    const float* b_fh_v   = (const float*)d_in[9];
    const float* W_ioux_l = (const float*)d_in[10];
    const float* b_ioux_l = (const float*)d_in[11];
    const float* W_iouh_l = (const float*)d_in[12];
    const float* b_iouh_l = (const float*)d_in[13];
    const float* W_fx_l   = (const float*)d_in[14];
    const float* b_fx_l   = (const float*)d_in[15];
    const float* W_fh_l   = (const float*)d_in[16];
    const float* b_fh_l   = (const float*)d_in[17];
    const float* W_type   = (const float*)d_in[18];
    const float* b_type   = (const float*)d_in[19];
    float* h_out = (float*)d_out;

    float *p_ioux_v, *p_ioux_l, *p_fx_v, *p_fx_l;
    float *p_hsum, *p_hsiou_v, *p_hsiou_l, *p_fh_v, *p_fh_l;
    cudaGetSymbolAddress((void**)&p_ioux_v,  g_ioux_v);
    cudaGetSymbolAddress((void**)&p_ioux_l,  g_ioux_l);
    cudaGetSymbolAddress((void**)&p_fx_v,    g_fx_v);
    cudaGetSymbolAddress((void**)&p_fx_l,    g_fx_l);
    cudaGetSymbolAddress((void**)&p_hsum,    g_hsum);
    cudaGetSymbolAddress((void**)&p_hsiou_v, g_hsiou_v);
    cudaGetSymbolAddress((void**)&p_hsiou_l, g_hsiou_l);
    cudaGetSymbolAddress((void**)&p_fh_v,    g_fh_v);
    cudaGetSymbolAddress((void**)&p_fh_l,    g_fh_l);

    const int mt = (NNODES + 63) / 64;  // 86

    // precompute: x @ {W_ioux, W_fx} for both modalities (+bias)
    gemm512<<<dim3(1536 / 128, mt), 256>>>(x, W_ioux_v, b_ioux_v, p_ioux_v, NNODES, 1536);
    gemm512<<<dim3(1536 / 128, mt), 256>>>(x, W_ioux_l, b_ioux_l, p_ioux_l, NNODES, 1536);
    gemm512<<<dim3(512 / 128,  mt), 256>>>(x, W_fx_v,   b_fx_v,   p_fx_v,   NNODES, 512);
    gemm512<<<dim3(512 / 128,  mt), 256>>>(x, W_fx_l,   b_fx_l,   p_fx_l,   NNODES, 512);
    sel_kernel<<<(NNODES + 7) / 8, 256>>>(x, W_type, b_type);
    leaf_kernel<<<(NLEAF * DIM) / 256, 256>>>(b_iouh_v, b_iouh_l, h_out);

    static const int ST[8] = {0, 1, 5, 21, 85, 341, 1365, 5461};
    for (int l = 5; l >= 0; --l) {
        int s  = ST[l];
        int S1 = ST[l + 1];
        int E  = ST[l + 1] - ST[l];
        int gE = (E * DIM + 255) / 256;
        int mE  = (E + 63) / 64;
        int mE4 = (4 * E + 63) / 64;
        hsum_kernel<<<gE, 256>>>(h_out, S1, E);
        gemm512<<<dim3(12, mE), 256>>>(p_hsum, W_iouh_v, nullptr, p_hsiou_v, E, 1536);
        gemm512<<<dim3(12, mE), 256>>>(p_hsum, W_iouh_l, nullptr, p_hsiou_l, E, 1536);
        gemm512<<<dim3(4, mE4), 256>>>(h_out + (size_t)S1 * DIM, W_fh_v, nullptr, p_fh_v, 4 * E, 512);
        gemm512<<<dim3(4, mE4), 256>>>(h_out + (size_t)S1 * DIM, W_fh_l, nullptr, p_fh_l, 4 * E, 512);
        gates_kernel<<<gE, 256>>>(s, S1, E, b_iouh_v, b_iouh_l, b_fh_v, b_fh_l, h_out);
    }
}

// round 2
// speedup vs baseline: 1.4519x; 1.4519x over previous
#include <cuda_runtime.h>
#include <math.h>

#define NNODES 5461          // (4^7-1)/3
#define LEAF_START 1365
#define NLEAF 4096
#define DIM 512

typedef unsigned long long ull;

// ---------------- scratch ----------------
__device__ float g_pre[(size_t)NNODES * 4096];   // [iou_v|iou_l|fx_v|fx_l] per node
__device__ float g_hsiou[1024 * 3072];           // [iou_v|iou_l] per level node
__device__ float g_fh[4096 * 1024];              // [fh_v|fh_l] per child row
__device__ float g_c[NNODES * DIM];
__device__ float g_Wcat[512 * 4096];
__device__ float g_bcat[4096];
__device__ float g_Wiouh[512 * 3072];
__device__ float g_Wfh[512 * 1024];
__device__ int   g_sel[NNODES];

// ---------------- packed f32x2 helpers ----------------
__device__ __forceinline__ ull f2_pack(float lo, float hi) {
    ull r; asm("mov.b64 %0, {%1, %2};" : "=l"(r) : "f"(lo), "f"(hi)); return r;
}
__device__ __forceinline__ void f2_fma(ull& d, ull a, ull b) {
    asm("fma.rn.f32x2 %0, %1, %2, %3;" : "=l"(d) : "l"(a), "l"(b), "l"(d));
}
__device__ __forceinline__ float2 f2_unpack(ull v) {
    float2 f; asm("mov.b64 {%0, %1}, %2;" : "=f"(f.x), "=f"(f.y) : "l"(v)); return f;
}
__device__ __forceinline__ float sigmf(float x) { return 1.0f / (1.0f + expf(-x)); }

// ---------------- weight packing ----------------
__global__ void pack_main(const float* __restrict__ Wi_v, const float* __restrict__ Wi_l,
                          const float* __restrict__ Wf_v, const float* __restrict__ Wf_l,
                          const float* __restrict__ bi_v, const float* __restrict__ bi_l,
                          const float* __restrict__ bf_v, const float* __restrict__ bf_l)
{
    int idx = blockIdx.x * blockDim.x + threadIdx.x;
    if (idx >= 512 * 4096) return;
    int k = idx >> 12, c = idx & 4095;
    float v;
    if (c < 1536)      v = Wi_v[k * 1536 + c];
    else if (c < 3072) v = Wi_l[k * 1536 + c - 1536];
    else if (c < 3584) v = Wf_v[k * 512 + c - 3072];
    else               v = Wf_l[k * 512 + c - 3584];
    g_Wcat[idx] = v;
    if (k == 0) {
        float b;
        if (c < 1536)      b = bi_v[c];
        else if (c < 3072) b = bi_l[c - 1536];
        else if (c < 3584) b = bf_v[c - 3072];
        else               b = bf_l[c - 3584];
        g_bcat[c] = b;
    }
}

__global__ void pack2(const float* __restrict__ Wv, const float* __restrict__ Wl,
                      float* __restrict__ dst, int half)
{
    int idx = blockIdx.x * blockDim.x + threadIdx.x;
    int Nc = half * 2;
    if (idx >= 512 * Nc) return;
    int k = idx / Nc, c = idx % Nc;
    dst[idx] = (c < half) ? Wv[k * half + c] : Wl[k * half + c - half];
}

// ---------------- GEMM: C[M,Nc] = A[M,512] @ B[512,Nc] (+bias) ----------------
// BM=128 BN=128 BK=16, 256 threads, 8x8 microtile, double-buffered, FFMA2 inner.
// sum4: A-row r = sum of global rows 4r..4r+3 (fused h_sum).
#define BM 128
#define BN 128
#define BK 16

__global__ void __launch_bounds__(256, 2) gemm_f2(
    const float* __restrict__ A, const float* __restrict__ B,
    const float* __restrict__ bias, float* __restrict__ C,
    int M, int Nc, int sum4)
{
    __shared__ __align__(16) ull   Asd[2][BK][BM];   // value-duplicated pairs
    __shared__ __align__(16) float Bs[2][BK][BN];

    const int tid  = threadIdx.x;
    const int row0 = blockIdx.y * BM;
    const int col0 = blockIdx.x * BN;
    const int tx   = tid & 15;        // 16 col groups of 8
    const int ty   = tid >> 4;        // 16 row groups of 8
    const int ar   = tid >> 2;        // 0..63  (rows ar, ar+64)
    const int ac   = (tid & 3) * 4;   // k-chunk of 4 floats
    const int br   = tid >> 5;        // 0..7   (rows br, br+8)
    const int bc   = (tid & 31) * 4;

    ull acc[8][4];
#pragma unroll
    for (int i = 0; i < 8; i++)
#pragma unroll
        for (int j = 0; j < 4; j++) acc[i][j] = 0ull;

    const float* Bp = B + (size_t)br * Nc + col0 + bc;

    auto loadA = [&](int k0, int r) -> float4 {
        int gr = row0 + r;
        float4 v = make_float4(0.f, 0.f, 0.f, 0.f);
        if (gr < M) {
            const float* p = A + (size_t)(sum4 ? 4 * gr : gr) * DIM + k0 + ac;
            v = *(const float4*)p;
            if (sum4) {
                float4 v1 = *(const float4*)(p + DIM);
                float4 v2 = *(const float4*)(p + 2 * DIM);
                float4 v3 = *(const float4*)(p + 3 * DIM);
                v.x += v1.x + v2.x + v3.x;
                v.y += v1.y + v2.y + v3.y;
                v.z += v1.z + v2.z + v3.z;
                v.w += v1.w + v2.w + v3.w;
            }
        }
        return v;
    };

    auto fill = [&](int buf, float4 a0, float4 a1, float4 b0, float4 b1) {
        Asd[buf][ac + 0][ar]      = f2_pack(a0.x, a0.x);
        Asd[buf][ac + 1][ar]      = f2_pack(a0.y, a0.y);
        Asd[buf][ac + 2][ar]      = f2_pack(a0.z, a0.z);
        Asd[buf][ac + 3][ar]      = f2_pack(a0.w, a0.w);
        Asd[buf][ac + 0][ar + 64] = f2_pack(a1.x, a1.x);
        Asd[buf][ac + 1][ar + 64] = f2_pack(a1.y, a1.y);
        Asd[buf][ac + 2][ar + 64] = f2_pack(a1.z, a1.z);
        Asd[buf][ac + 3][ar + 64] = f2_pack(a1.w, a1.w);
        *(float4*)&Bs[buf][br][bc]     = b0;
        *(float4*)&Bs[buf][br + 8][bc] = b1;
    };

    float4 pa0 = loadA(0, ar);
    float4 pa1 = loadA(0, ar + 64);
    float4 pb0 = *(const float4*)(Bp);
    float4 pb1 = *(const float4*)(Bp + 8 * (size_t)Nc);

    int buf = 0;
    for (int k0 = 0; k0 < DIM; k0 += BK) {
        fill(buf, pa0, pa1, pb0, pb1);
        __syncthreads();
        if (k0 + BK < DIM) {
            pa0 = loadA(k0 + BK, ar);
            pa1 = loadA(k0 + BK, ar + 64);
            pb0 = *(const float4*)(Bp + (size_t)(k0 + BK) * Nc);
            pb1 = *(const float4*)(Bp + (size_t)(k0 + BK + 8) * Nc);
        }
#pragma unroll
        for (int kk = 0; kk < BK; kk++) {
            ulonglong2 a01 = *(const ulonglong2*)&Asd[buf][kk][ty * 8 + 0];
            ulonglong2 a23 = *(const ulonglong2*)&Asd[buf][kk][ty * 8 + 2];
            ulonglong2 a45 = *(const ulonglong2*)&Asd[buf][kk][ty * 8 + 4];
            ulonglong2 a67 = *(const ulonglong2*)&Asd[buf][kk][ty * 8 + 6];
            ulonglong2 b01 = *(const ulonglong2*)&Bs[buf][kk][tx * 8];
            ulonglong2 b23 = *(const ulonglong2*)&Bs[buf][kk][tx * 8 + 4];
            f2_fma(acc[0][0], a01.x, b01.x); f2_fma(acc[0][1], a01.x, b01.y);
            f2_fma(acc[0][2], a01.x, b23.x); f2_fma(acc[0][3], a01.x, b23.y);
            f2_fma(acc[1][0], a01.y, b01.x); f2_fma(acc[1][1], a01.y, b01.y);
            f2_fma(acc[1][2], a01.y, b23.x); f2_fma(acc[1][3], a01.y, b23.y);
            f2_fma(acc[2][0], a23.x, b01.x); f2_fma(acc[2][1], a23.x, b01.y);
            f2_fma(acc[2][2], a23.x, b23.x); f2_fma(acc[2][3], a23.x, b23.y);
            f2_fma(acc[3][0], a23.y, b01.x); f2_fma(acc[3][1], a23.y, b01.y);
            f2_fma(acc[3][2], a23.y, b23.x); f2_fma(acc[3][3], a23.y, b23.y);
            f2_fma(acc[4][0], a45.x, b01.x); f2_fma(acc[4][1], a45.x, b01.y);
            f2_fma(acc[4][2], a45.x, b23.x); f2_fma(acc[4][3], a45.x, b23.y);
            f2_fma(acc[5][0], a45.y, b01.x); f2_fma(acc[5][1], a45.y, b01.y);
            f2_fma(acc[5][2], a45.y, b23.x); f2_fma(acc[5][3], a45.y, b23.y);
            f2_fma(acc[6][0], a67.x, b01.x); f2_fma(acc[6][1], a67.x, b01.y);
            f2_fma(acc[6][2], a67.x, b23.x); f2_fma(acc[6][3], a67.x, b23.y);
            f2_fma(acc[7][0], a67.y, b01.x); f2_fma(acc[7][1], a67.y, b01.y);
            f2_fma(acc[7][2], a67.y, b23.x); f2_fma(acc[7][3], a67.y, b23.y);
        }
        buf ^= 1;
    }

    const int ccol = col0 + tx * 8;
    float bv[8];
#pragma unroll
    for (int j = 0; j < 8; j++) bv[j] = bias ? bias[ccol + j] : 0.f;
#pragma unroll
    for (int i = 0; i < 8; i++) {
        int r = row0 + ty * 8 + i;
        if (r < M) {
            float2 v0 = f2_unpack(acc[i][0]);
            float2 v1 = f2_unpack(acc[i][1]);
            float2 v2 = f2_unpack(acc[i][2]);
            float2 v3 = f2_unpack(acc[i][3]);
            float* Crow = C + (size_t)r * Nc + ccol;
            *(float4*)(Crow)     = make_float4(v0.x + bv[0], v0.y + bv[1], v1.x + bv[2], v1.y + bv[3]);
            *(float4*)(Crow + 4) = make_float4(v2.x + bv[4], v2.y + bv[5], v3.x + bv[6], v3.y + bv[7]);
        }
    }
}

// ---------------- modality selection ----------------
__global__ void sel_kernel(const float* __restrict__ x,
                           const float* __restrict__ Wt,
                           const float* __restrict__ bt)
{
    int n = blockIdx.x * (blockDim.x >> 5) + (threadIdx.x >> 5);
    int lane = threadIdx.x & 31;
    if (n >= NNODES) return;
    float s0 = 0.f, s1 = 0.f;
    const float* xr = x + (size_t)n * DIM;
#pragma unroll 4
    for (int k = lane; k < DIM; k += 32) {
        float xv = xr[k];
        s0 = fmaf(xv, Wt[k * 2 + 0], s0);
        s1 = fmaf(xv, Wt[k * 2 + 1], s1);
    }
#pragma unroll
    for (int o = 16; o > 0; o >>= 1) {
        s0 += __shfl_xor_sync(0xFFFFFFFFu, s0, o);
        s1 += __shfl_xor_sync(0xFFFFFFFFu, s1, o);
    }
    if (lane == 0) g_sel[n] = (s0 + bt[0] >= s1 + bt[1]) ? 1 : 0;
}

// ---------------- leaves ----------------
__global__ void leaf_kernel(const float* __restrict__ bi_v,
                            const float* __restrict__ bi_l,
                            float* __restrict__ h_out)
{
    int idx = blockIdx.x * blockDim.x + threadIdx.x;
    if (idx >= NLEAF * DIM) return;
    int n = LEAF_START + (idx >> 9);
    int j = idx & (DIM - 1);
    int sl = g_sel[n];
    const float* bi = sl ? bi_l : bi_v;
    size_t base = (size_t)n * 4096 + (size_t)sl * 1536;
    float ig = g_pre[base + j]        + bi[j];
    float og = g_pre[base + 512 + j]  + bi[512 + j];
    float ug = g_pre[base + 1024 + j] + bi[1024 + j];
    float cc = sigmf(ig) * tanhf(ug);
    float hh = sigmf(og) * tanhf(cc);
    g_c[(size_t)n * DIM + j] = cc;
    h_out[(size_t)n * DIM + j] = hh;
}

// ---------------- internal-node gates ----------------
__global__ void gates_kernel(int s, int S1, int E,
                             const float* __restrict__ bi_v,
                             const float* __restrict__ bi_l,
                             const float* __restrict__ bf_v,
                             const float* __restrict__ bf_l,
                             float* __restrict__ h_out)
{
    int idx = blockIdx.x * blockDim.x + threadIdx.x;
    if (idx >= E * DIM) return;
    int i = idx >> 9, j = idx & (DIM - 1);
    int n = s + i;
    int sl = g_sel[n];
    const float* bi = sl ? bi_l : bi_v;
    const float* bf = sl ? bf_l : bf_v;
    size_t xb = (size_t)n * 4096 + (size_t)sl * 1536;
    size_t hb = (size_t)i * 3072 + (size_t)sl * 1536;
    float ig = g_pre[xb + j]        + g_hsiou[hb + j]        + bi[j];
    float og = g_pre[xb + 512 + j]  + g_hsiou[hb + 512 + j]  + bi[512 + j];
    float ug = g_pre[xb + 1024 + j] + g_hsiou[hb + 1024 + j] + bi[1024 + j];
    float fxv = g_pre[(size_t)n * 4096 + 3072 + (size_t)sl * 512 + j] + bf[j];

    float cc = sigmf(ig) * tanhf(ug);
    size_t c0 = (size_t)(S1 + 4 * i) * DIM + j;
    size_t f0 = (size_t)(4 * i) * 1024 + (size_t)sl * 512 + j;
#pragma unroll
    for (int k = 0; k < 4; k++) {
        float f = sigmf(g_fh[f0 + (size_t)k * 1024] + fxv);
        cc = fmaf(f, g_c[c0 + (size_t)k * DIM], cc);
    }
    float hh = sigmf(og) * tanhf(cc);
    g_c[(size_t)n * DIM + j] = cc;
    h_out[(size_t)n * DIM + j] = hh;
}

// ---------------- launch ----------------
extern "C" void kernel_launch(void* const* d_in, const int* in_sizes, int n_in,
                              void* d_out, int out_size)
{
    const float* x        = (const float*)d_in[0];
    const float* W_ioux_v = (const float*)d_in[2];
    const float* b_ioux_v = (const float*)d_in[3];
    const float* W_iouh_v = (const float*)d_in[4];
    const float* b_iouh_v = (const float*)d_in[5];
    const float* W_fx_v   = (const float*)d_in[6];
    const float* b_fx_v   = (const float*)d_in[7];
    const float* W_fh_v   = (const float*)d_in[8];
    const float* b_fh_v   = (const float*)d_in[9];
    const float* W_ioux_l = (const float*)d_in[10];
    const float* b_ioux_l = (const float*)d_in[11];
    const float* W_iouh_l = (const float*)d_in[12];
    const float* b_iouh_l = (const float*)d_in[13];
    const float* W_fx_l   = (const float*)d_in[14];
    const float* b_fx_l   = (const float*)d_in[15];
    const float* W_fh_l   = (const float*)d_in[16];
    const float* b_fh_l   = (const float*)d_in[17];
    const float* W_type   = (const float*)d_in[18];
    const float* b_type   = (const float*)d_in[19];
    float* h_out = (float*)d_out;

    float *p_pre, *p_hsiou, *p_fh, *p_Wcat, *p_bcat, *p_Wiouh, *p_Wfh;
    cudaGetSymbolAddress((void**)&p_pre,   g_pre);
    cudaGetSymbolAddress((void**)&p_hsiou, g_hsiou);
    cudaGetSymbolAddress((void**)&p_fh,    g_fh);
    cudaGetSymbolAddress((void**)&p_Wcat,  g_Wcat);
    cudaGetSymbolAddress((void**)&p_bcat,  g_bcat);
    cudaGetSymbolAddress((void**)&p_Wiouh, g_Wiouh);
    cudaGetSymbolAddress((void**)&p_Wfh,   g_Wfh);

    // pack weights
    pack_main<<<(512 * 4096) / 256, 256>>>(W_ioux_v, W_ioux_l, W_fx_v, W_fx_l,
                                           b_ioux_v, b_ioux_l, b_fx_v, b_fx_l);
    pack2<<<(512 * 3072) / 256, 256>>>(W_iouh_v, W_iouh_l, p_Wiouh, 1536);
    pack2<<<(512 * 1024) / 256, 256>>>(W_fh_v, W_fh_l, p_Wfh, 512);

    // precompute x @ [W_ioux_v|W_ioux_l|W_fx_v|W_fx_l] + biases
    gemm_f2<<<dim3(4096 / BN, (NNODES + BM - 1) / BM), 256>>>(
        x, p_Wcat, p_bcat, p_pre, NNODES, 4096, 0);
    sel_kernel<<<(NNODES + 7) / 8, 256>>>(x, W_type, b_type);
    leaf_kernel<<<(NLEAF * DIM) / 256, 256>>>(b_iouh_v, b_iouh_l, h_out);

    static const int ST[8] = {0, 1, 5, 21, 85, 341, 1365, 5461};
    for (int l = 5; l >= 0; --l) {
        int s  = ST[l];
        int S1 = ST[l + 1];
        int E  = ST[l + 1] - ST[l];
        // iouh GEMM with fused h_sum (A-row = sum of 4 child h rows)
        gemm_f2<<<dim3(3072 / BN, (E + BM - 1) / BM), 256>>>(
            h_out + (size_t)S1 * DIM, p_Wiouh, nullptr, p_hsiou, E, 3072, 1);
        // fh GEMM over child h rows
        gemm_f2<<<dim3(1024 / BN, (4 * E + BM - 1) / BM), 256>>>(
            h_out + (size_t)S1 * DIM, p_Wfh, nullptr, p_fh, 4 * E, 1024, 0);
        gates_kernel<<<(E * DIM + 255) / 256, 256>>>(
            s, S1, E, b_iouh_v, b_iouh_l, b_fh_v, b_fh_l, h_out);
    }
}

// round 4
// speedup vs baseline: 3.1386x; 2.1617x over previous
#include <cuda_runtime.h>
#include <cuda_bf16.h>
#include <math.h>
#include <stdint.h>

#define NNODES 5461
#define LEAF_START 1365
#define NLEAF 4096
#define DIM 512
#define KP 1536           // split-K: [hi | lo | hi]
#define BKC 64            // bf16 K per chunk
#define NIT (KP / BKC)    // 24

// ---------------- scratch (__device__ globals) ----------------
__device__ __align__(16) __nv_bfloat16 g_xsplit[(size_t)NNODES * KP];
__device__ __align__(16) __nv_bfloat16 g_hsplit[(size_t)NNODES * KP];
__device__ __align__(16) __nv_bfloat16 g_hsumsplit[1024 * KP];
__device__ __align__(16) __nv_bfloat16 g_Wcat_b[4096 * KP];
__device__ __align__(16) __nv_bfloat16 g_Wiouh_b[3072 * KP];
__device__ __align__(16) __nv_bfloat16 g_Wfh_b[1024 * KP];
__device__ float g_bcat[4096];
__device__ float g_pre[(size_t)NNODES * 4096];   // [iou_v|iou_l|fx_v|fx_l]
__device__ float g_hsiou[1024 * 3072];           // [iou_v|iou_l]
__device__ float g_fh[4096 * 1024];              // [fh_v|fh_l]
__device__ float g_c[NNODES * DIM];
__device__ int   g_sel[NNODES];

__device__ __forceinline__ float sigmf(float x) { return 1.0f / (1.0f + expf(-x)); }

// ---------------- PTX helpers (sm_100-safe: cp.async + ldmatrix + mma.sync) ----------------
__device__ __forceinline__ uint32_t smem_u32(const void* p) {
    uint32_t a;
    asm("{ .reg .u64 t; cvta.to.shared.u64 t, %1; cvt.u32.u64 %0, t; }" : "=r"(a) : "l"(p));
    return a;
}
__device__ __forceinline__ void cpasync16(uint32_t dst, const void* src, int srcsize) {
    asm volatile("cp.async.cg.shared.global [%0], [%1], 16, %2;"
                 :: "r"(dst), "l"(src), "r"(srcsize) : "memory");
}
#define CP_COMMIT() asm volatile("cp.async.commit_group;" ::: "memory")
#define CP_WAIT1()  asm volatile("cp.async.wait_group 1;" ::: "memory")
#define CP_WAIT0()  asm volatile("cp.async.wait_group 0;" ::: "memory")

#define LDSM4(r, addr) \
    asm volatile("ldmatrix.sync.aligned.m8n8.x4.shared.b16 {%0,%1,%2,%3}, [%4];" \
                 : "=r"((r)[0]), "=r"((r)[1]), "=r"((r)[2]), "=r"((r)[3]) : "r"(addr))

#define MMA16816(d, a, b0_, b1_) \
    asm volatile("mma.sync.aligned.m16n8k16.row.col.f32.bf16.bf16.f32 " \
                 "{%0,%1,%2,%3}, {%4,%5,%6,%7}, {%8,%9}, {%0,%1,%2,%3};" \
                 : "+f"((d)[0]), "+f"((d)[1]), "+f"((d)[2]), "+f"((d)[3]) \
                 : "r"((a)[0]), "r"((a)[1]), "r"((a)[2]), "r"((a)[3]), "r"(b0_), "r"(b1_))

__device__ __forceinline__ uint32_t sw128(uint32_t off) {   // Swizzle<3,4,3>
    return off ^ ((off >> 3) & 0x70);
}

// ---------------- tensor-core GEMM via mma.sync ----------------
// C[M,Nc] = A[M,KP] @ B[Nc,KP]^T (+bias).  A,B bf16 K-major.
// BM=128 BN=128 BK=64, 256 threads (8 warps, 4x2), warp tile 32x64, cp.async 2-stage.
#define TILE_BYTES 16384              // 128 rows x 128B
#define SMEM_TOTAL_MMA (4 * TILE_BYTES)

__global__ void __launch_bounds__(256, 1) gemm_mma(
    const __nv_bfloat16* __restrict__ A, const __nv_bfloat16* __restrict__ B,
    const float* __restrict__ bias, float* __restrict__ C, int M, int Nc)
{
    extern __shared__ char smem[];
    const uint32_t sb = smem_u32(smem);
    const int tid  = threadIdx.x;
    const int wid  = tid >> 5;
    const int lane = tid & 31;
    const int wm   = wid & 3;          // 4 warps over M (32 rows each)
    const int wn   = wid >> 2;         // 2 warps over N (64 cols each)
    const int row0 = blockIdx.y * 128;
    const int col0 = blockIdx.x * 128;

    // ---- cp.async mapping: thread t loads 4x16B of A and 4x16B of B ----
    const int lrow = tid >> 1;                 // 0..127
    const int lch0 = (tid & 1) * 4;            // chunk base (16B units within 128B row)
    const int a_sz = (row0 + lrow < M) ? 16 : 0;
    const __nv_bfloat16* gA = A + (size_t)(row0 + lrow) * KP + lch0 * 8;
    const __nv_bfloat16* gB = B + (size_t)(col0 + lrow) * KP + lch0 * 8;
    uint32_t sA[4], sB[4];
#pragma unroll
    for (int i = 0; i < 4; i++) {
        uint32_t off = sw128((uint32_t)(lrow * 128 + (lch0 + i) * 16));
        sA[i] = sb + off;
        sB[i] = sb + 2 * TILE_BYTES + off;
    }

    // ---- ldmatrix lane-address offsets (within a tile buffer) ----
    uint32_t offA[2][4], offB[4][4];
#pragma unroll
    for (int mi = 0; mi < 2; mi++)
#pragma unroll
        for (int kb = 0; kb < 4; kb++) {
            int r = wm * 32 + mi * 16 + (lane & 15);
            int k = kb * 16 + ((lane >> 4) << 3);
            offA[mi][kb] = sw128((uint32_t)(r * 128 + k * 2));
        }
#pragma unroll
    for (int ni = 0; ni < 4; ni++)
#pragma unroll
        for (int kb = 0; kb < 4; kb++) {
            int r = wn * 64 + ni * 16 + (lane & 7) + ((lane >> 4) << 3);
            int k = kb * 16 + (((lane >> 3) & 1) << 3);
            offB[ni][kb] = sw128((uint32_t)(r * 128 + k * 2));
        }

    float acc[2][8][4];
#pragma unroll
    for (int mi = 0; mi < 2; mi++)
#pragma unroll
        for (int nj = 0; nj < 8; nj++)
#pragma unroll
            for (int q = 0; q < 4; q++) acc[mi][nj][q] = 0.f;

    // ---- prologue: load chunk 0 into buf 0 ----
#pragma unroll
    for (int i = 0; i < 4; i++) {
        cpasync16(sA[i], gA + i * 8, a_sz);
        cpasync16(sB[i], gB + i * 8, 16);
    }
    CP_COMMIT();

    for (int c = 0; c < NIT; c++) {
        if (c + 1 < NIT) {
            uint32_t bsel = ((c + 1) & 1) * TILE_BYTES;
            const __nv_bfloat16* pa = gA + (c + 1) * BKC;
            const __nv_bfloat16* pb = gB + (c + 1) * BKC;
#pragma unroll
            for (int i = 0; i < 4; i++) {
                cpasync16(sA[i] + bsel, pa + i * 8, a_sz);
                cpasync16(sB[i] + bsel, pb + i * 8, 16);
            }
            CP_COMMIT();
            CP_WAIT1();
        } else {
            CP_WAIT0();
        }
        __syncthreads();

        const uint32_t abase = sb + (c & 1) * TILE_BYTES;
        const uint32_t bbase = sb + 2 * TILE_BYTES + (c & 1) * TILE_BYTES;
#pragma unroll
        for (int kb = 0; kb < 4; kb++) {
            uint32_t a0[4], a1[4];
            LDSM4(a0, abase + offA[0][kb]);
            LDSM4(a1, abase + offA[1][kb]);
#pragma unroll
            for (int ni = 0; ni < 4; ni++) {
                uint32_t bt[4];
                LDSM4(bt, bbase + offB[ni][kb]);
                MMA16816(acc[0][2 * ni],     a0, bt[0], bt[1]);
                MMA16816(acc[0][2 * ni + 1], a0, bt[2], bt[3]);
                MMA16816(acc[1][2 * ni],     a1, bt[0], bt[1]);
                MMA16816(acc[1][2 * ni + 1], a1, bt[2], bt[3]);
            }
        }
        __syncthreads();
    }

    // ---- epilogue ----
#pragma unroll
    for (int mi = 0; mi < 2; mi++) {
        int r0 = row0 + wm * 32 + mi * 16 + (lane >> 2);
#pragma unroll
        for (int nj = 0; nj < 8; nj++) {
            int col = col0 + wn * 64 + nj * 8 + (lane & 3) * 2;
            float b0 = 0.f, b1 = 0.f;
            if (bias) { b0 = bias[col]; b1 = bias[col + 1]; }
            if (r0 < M) {
                float2 v = make_float2(acc[mi][nj][0] + b0, acc[mi][nj][1] + b1);
                *(float2*)(C + (size_t)r0 * Nc + col) = v;
            }
            if (r0 + 8 < M) {
                float2 v = make_float2(acc[mi][nj][2] + b0, acc[mi][nj][3] + b1);
                *(float2*)(C + (size_t)(r0 + 8) * Nc + col) = v;
            }
        }
    }
}

// ---------------- bf16 split helpers ----------------
__device__ __forceinline__ void bsplit(float v, __nv_bfloat16& h, __nv_bfloat16& l) {
    h = __float2bfloat16(v);
    l = __float2bfloat16(v - __bfloat162float(h));
}

// ---------------- weight packing: dst[n][k'] K-major, [hi|hi|lo] ----------------
__global__ void pack_cat(const float* __restrict__ Wi_v, const float* __restrict__ Wi_l,
                         const float* __restrict__ Wf_v, const float* __restrict__ Wf_l,
                         const float* __restrict__ bi_v, const float* __restrict__ bi_l,
                         const float* __restrict__ bf_v, const float* __restrict__ bf_l)
{
    int idx = blockIdx.x * blockDim.x + threadIdx.x;   // kb*4096 + n
    if (idx >= 4096 * 64) return;
    int kb = idx >> 12, n = idx & 4095;
    const float* W; int col, ld;
    if (n < 1536)      { W = Wi_v; col = n;        ld = 1536; }
    else if (n < 3072) { W = Wi_l; col = n - 1536; ld = 1536; }
    else if (n < 3584) { W = Wf_v; col = n - 3072; ld = 512;  }
    else               { W = Wf_l; col = n - 3584; ld = 512;  }
    __nv_bfloat16 hi8[8], lo8[8];
#pragma unroll
    for (int j = 0; j < 8; j++) bsplit(W[(size_t)(kb * 8 + j) * ld + col], hi8[j], lo8[j]);
    size_t b = (size_t)n * KP + kb * 8;
    *(uint4*)&g_Wcat_b[b]        = *(uint4*)hi8;
    *(uint4*)&g_Wcat_b[b + 512]  = *(uint4*)hi8;
    *(uint4*)&g_Wcat_b[b + 1024] = *(uint4*)lo8;
    if (kb == 0) {
        float bv;
        if (n < 1536)      bv = bi_v[n];
        else if (n < 3072) bv = bi_l[n - 1536];
        else if (n < 3584) bv = bf_v[n - 3072];
        else               bv = bf_l[n - 3584];
        g_bcat[n] = bv;
    }
}

__global__ void pack_b2(const float* __restrict__ Wv, const float* __restrict__ Wl,
                        __nv_bfloat16* __restrict__ dst, int halfc)
{
    int rows = 2 * halfc;
    int idx = blockIdx.x * blockDim.x + threadIdx.x;   // kb*rows + n
    if (idx >= rows * 64) return;
    int kb = idx / rows, n = idx % rows;
    const float* W = (n < halfc) ? Wv : Wl;
    int col = (n < halfc) ? n : n - halfc;
    __nv_bfloat16 hi8[8], lo8[8];
#pragma unroll
    for (int j = 0; j < 8; j++) bsplit(W[(size_t)(kb * 8 + j) * halfc + col], hi8[j], lo8[j]);
    size_t b = (size_t)n * KP + kb * 8;
    *(uint4*)&dst[b]        = *(uint4*)hi8;
    *(uint4*)&dst[b + 512]  = *(uint4*)hi8;
    *(uint4*)&dst[b + 1024] = *(uint4*)lo8;
}

// ---------------- x split: [hi|lo|hi] ----------------
__global__ void split_x(const float* __restrict__ x)
{
    int idx = blockIdx.x * blockDim.x + threadIdx.x;   // n*64 + kb
    if (idx >= NNODES * 64) return;
    int n = idx >> 6, kb = idx & 63;
    __nv_bfloat16 hi8[8], lo8[8];
    const float* p = x + (size_t)n * DIM + kb * 8;
#pragma unroll
    for (int j = 0; j < 8; j++) bsplit(p[j], hi8[j], lo8[j]);
    size_t b = (size_t)n * KP + kb * 8;
    *(uint4*)&g_xsplit[b]        = *(uint4*)hi8;
    *(uint4*)&g_xsplit[b + 512]  = *(uint4*)lo8;
    *(uint4*)&g_xsplit[b + 1024] = *(uint4*)hi8;
}

// ---------------- modality selection ----------------
__global__ void sel_kernel(const float* __restrict__ x,
                           const float* __restrict__ Wt,
                           const float* __restrict__ bt)
{
    int n = blockIdx.x * (blockDim.x >> 5) + (threadIdx.x >> 5);
    int lane = threadIdx.x & 31;
    if (n >= NNODES) return;
    float s0 = 0.f, s1 = 0.f;
    const float* xr = x + (size_t)n * DIM;
#pragma unroll 4
    for (int k = lane; k < DIM; k += 32) {
        float xv = xr[k];
        s0 = fmaf(xv, Wt[k * 2 + 0], s0);
        s1 = fmaf(xv, Wt[k * 2 + 1], s1);
    }
#pragma unroll
    for (int o = 16; o > 0; o >>= 1) {
        s0 += __shfl_xor_sync(0xFFFFFFFFu, s0, o);
        s1 += __shfl_xor_sync(0xFFFFFFFFu, s1, o);
    }
    if (lane == 0) g_sel[n] = (s0 + bt[0] >= s1 + bt[1]) ? 1 : 0;
}

__device__ __forceinline__ void write_h(int n, int j, float h, float* __restrict__ h_out) {
    h_out[(size_t)n * DIM + j] = h;
    __nv_bfloat16 hh, hl;
    bsplit(h, hh, hl);
    size_t b = (size_t)n * KP + j;
    g_hsplit[b]        = hh;
    g_hsplit[b + 512]  = hl;
    g_hsplit[b + 1024] = hh;
}

// ---------------- leaves ----------------
__global__ void leaf_kernel(const float* __restrict__ bi_v,
                            const float* __restrict__ bi_l,
                            float* __restrict__ h_out)
{
    int idx = blockIdx.x * blockDim.x + threadIdx.x;
    if (idx >= NLEAF * DIM) return;
    int n = LEAF_START + (idx >> 9);
    int j = idx & (DIM - 1);
    int sl = g_sel[n];
    const float* bi = sl ? bi_l : bi_v;
    size_t base = (size_t)n * 4096 + (size_t)sl * 1536;
    float ig = g_pre[base + j]        + bi[j];
    float og = g_pre[base + 512 + j]  + bi[512 + j];
    float ug = g_pre[base + 1024 + j] + bi[1024 + j];
    float cc = sigmf(ig) * tanhf(ug);
    float hh = sigmf(og) * tanhf(cc);
    g_c[(size_t)n * DIM + j] = cc;
    write_h(n, j, hh, h_out);
}

// ---------------- h_sum (fp32) + split ----------------
__global__ void hsum_kernel(const float* __restrict__ h_all, int S1, int E)
{
    int idx = blockIdx.x * blockDim.x + threadIdx.x;
    if (idx >= E * DIM) return;
    int i = idx >> 9, j = idx & (DIM - 1);
    const float* b = h_all + (size_t)(S1 + 4 * i) * DIM + j;
    float s = (b[0] + b[DIM]) + (b[2 * DIM] + b[3 * DIM]);
    __nv_bfloat16 hh, hl;
    bsplit(s, hh, hl);
    size_t bb = (size_t)i * KP + j;
    g_hsumsplit[bb]        = hh;
    g_hsumsplit[bb + 512]  = hl;
    g_hsumsplit[bb + 1024] = hh;
}

// ---------------- internal-node gates ----------------
__global__ void gates_kernel(int s, int S1, int E,
                             const float* __restrict__ bi_v,
                             const float* __restrict__ bi_l,
                             const float* __restrict__ bf_v,
                             const float* __restrict__ bf_l,
                             float* __restrict__ h_out)
{
    int idx = blockIdx.x * blockDim.x + threadIdx.x;
    if (idx >= E * DIM) return;
    int i = idx >> 9, j = idx & (DIM - 1);
    int n = s + i;
    int sl = g_sel[n];
    const float* bi = sl ? bi_l : bi_v;
    const float* bf = sl ? bf_l : bf_v;
    size_t xb = (size_t)n * 4096 + (size_t)sl * 1536;
    size_t hb = (size_t)i * 3072 + (size_t)sl * 1536;
    float ig = g_pre[xb + j]        + g_hsiou[hb + j]        + bi[j];
    float og = g_pre[xb + 512 + j]  + g_hsiou[hb + 512 + j]  + bi[512 + j];
    float ug = g_pre[xb + 1024 + j] + g_hsiou[hb + 1024 + j] + bi[1024 + j];
    float fxv = g_pre[(size_t)n * 4096 + 3072 + (size_t)sl * 512 + j] + bf[j];

    float cc = sigmf(ig) * tanhf(ug);
    size_t c0 = (size_t)(S1 + 4 * i) * DIM + j;
    size_t f0 = (size_t)(4 * i) * 1024 + (size_t)sl * 512 + j;
#pragma unroll
    for (int k = 0; k < 4; k++) {
        float f = sigmf(g_fh[f0 + (size_t)k * 1024] + fxv);
        cc = fmaf(f, g_c[c0 + (size_t)k * DIM], cc);
    }
    float hh = sigmf(og) * tanhf(cc);
    g_c[(size_t)n * DIM + j] = cc;
    write_h(n, j, hh, h_out);
}

// ---------------- launch ----------------
extern "C" void kernel_launch(void* const* d_in, const int* in_sizes, int n_in,
                              void* d_out, int out_size)
{
    const float* x        = (const float*)d_in[0];
    const float* W_ioux_v = (const float*)d_in[2];
    const float* b_ioux_v = (const float*)d_in[3];
    const float* W_iouh_v = (const float*)d_in[4];
    const float* b_iouh_v = (const float*)d_in[5];
    const float* W_fx_v   = (const float*)d_in[6];
    const float* b_fx_v   = (const float*)d_in[7];
    const float* W_fh_v   = (const float*)d_in[8];
    const float* b_fh_v   = (const float*)d_in[9];
    const float* W_ioux_l = (const float*)d_in[10];
    const float* b_ioux_l = (const float*)d_in[11];
    const float* W_iouh_l = (const float*)d_in[12];
    const float* b_iouh_l = (const float*)d_in[13];
    const float* W_fx_l   = (const float*)d_in[14];
    const float* b_fx_l   = (const float*)d_in[15];
    const float* W_fh_l   = (const float*)d_in[16];
    const float* b_fh_l   = (const float*)d_in[17];
    const float* W_type   = (const float*)d_in[18];
    const float* b_type   = (const float*)d_in[19];
    float* h_out = (float*)d_out;

    cudaFuncSetAttribute(gemm_mma, cudaFuncAttributeMaxDynamicSharedMemorySize, SMEM_TOTAL_MMA);

    __nv_bfloat16 *p_xsplit, *p_hsplit, *p_hsumsplit, *p_Wcat, *p_Wiouh, *p_Wfh;
    float *p_bcat, *p_pre, *p_hsiou, *p_fh;
    cudaGetSymbolAddress((void**)&p_xsplit,    g_xsplit);
    cudaGetSymbolAddress((void**)&p_hsplit,    g_hsplit);
    cudaGetSymbolAddress((void**)&p_hsumsplit, g_hsumsplit);
    cudaGetSymbolAddress((void**)&p_Wcat,      g_Wcat_b);
    cudaGetSymbolAddress((void**)&p_Wiouh,     g_Wiouh_b);
    cudaGetSymbolAddress((void**)&p_Wfh,       g_Wfh_b);
    cudaGetSymbolAddress((void**)&p_bcat,      g_bcat);
    cudaGetSymbolAddress((void**)&p_pre,       g_pre);
    cudaGetSymbolAddress((void**)&p_hsiou,     g_hsiou);
    cudaGetSymbolAddress((void**)&p_fh,        g_fh);

    // pack weights + split x
    pack_cat<<<(4096 * 64) / 256, 256>>>(W_ioux_v, W_ioux_l, W_fx_v, W_fx_l,
                                         b_ioux_v, b_ioux_l, b_fx_v, b_fx_l);
    pack_b2<<<(3072 * 64) / 256, 256>>>(W_iouh_v, W_iouh_l, p_Wiouh, 1536);
    pack_b2<<<(1024 * 64) / 256, 256>>>(W_fh_v, W_fh_l, p_Wfh, 512);
    split_x<<<(NNODES * 64 + 255) / 256, 256>>>(x);
    sel_kernel<<<(NNODES + 7) / 8, 256>>>(x, W_type, b_type);

    // big precompute GEMM: [5461 x 4096] = xsplit @ Wcat^T + bcat
    gemm_mma<<<dim3(4096 / 128, (NNODES + 127) / 128), 256, SMEM_TOTAL_MMA>>>(
        p_xsplit, p_Wcat, p_bcat, p_pre, NNODES, 4096);

    leaf_kernel<<<(NLEAF * DIM) / 256, 256>>>(b_iouh_v, b_iouh_l, h_out);

    static const int ST[8] = {0, 1, 5, 21, 85, 341, 1365, 5461};
    for (int l = 5; l >= 0; --l) {
        int s  = ST[l];
        int S1 = ST[l + 1];
        int E  = ST[l + 1] - ST[l];
        hsum_kernel<<<(E * DIM + 255) / 256, 256>>>(h_out, S1, E);
        gemm_mma<<<dim3(3072 / 128, (E + 127) / 128), 256, SMEM_TOTAL_MMA>>>(
            p_hsumsplit, p_Wiouh, nullptr, p_hsiou, E, 3072);
        gemm_mma<<<dim3(1024 / 128, (4 * E + 127) / 128), 256, SMEM_TOTAL_MMA>>>(
            p_hsplit + (size_t)S1 * KP, p_Wfh, nullptr, p_fh, 4 * E, 1024);
        gates_kernel<<<(E * DIM + 255) / 256, 256>>>(
            s, S1, E, b_iouh_v, b_iouh_l, b_fh_v, b_fh_l, h_out);
    }
}

// round 5
// speedup vs baseline: 5.2693x; 1.6788x over previous
#include <cuda_runtime.h>
#include <cuda_bf16.h>
#include <math.h>
#include <stdint.h>

#define NNODES 5461
#define NINT 1365
#define LEAF_START 1365
#define NLEAF 4096
#define DIM 512
#define KP 1536           // split-K: [hi | lo | hi]
#define BKC 64
#define NIT (KP / BKC)    // 24

// ---------------- scratch ----------------
__device__ __align__(16) __nv_bfloat16 g_xsplit[(size_t)NNODES * KP];
__device__ __align__(16) __nv_bfloat16 g_hsplit[(size_t)NNODES * KP];
__device__ __align__(16) __nv_bfloat16 g_hsumsplit[1024 * KP];
__device__ __align__(16) __nv_bfloat16 g_Wmod[2][2048 * KP];     // [Wi_m|Wf_m]
__device__ __align__(16) __nv_bfloat16 g_Wiouh_m[2][1536 * KP];
__device__ __align__(16) __nv_bfloat16 g_Wfh_m[2][512 * KP];
__device__ float g_bmod[2][2048];
__device__ float g_pre[(size_t)NNODES * 2048];   // selected [iou|fx] per node
__device__ float g_hsiou[1024 * 1536];
__device__ float g_fh[4096 * 512];
__device__ float g_c[NNODES * DIM];
__device__ int   g_sel[NNODES];
__device__ int   g_gcnt[2];
__device__ int   g_gidx[2 * NNODES];
__device__ int   g_lcnt[12];
__device__ int   g_lidx_v[NINT];
__device__ int   g_lidx_l[NINT];

__device__ __forceinline__ float sigmf(float x) { return 1.0f / (1.0f + expf(-x)); }

// ---------------- PTX helpers ----------------
__device__ __forceinline__ uint32_t smem_u32(const void* p) {
    uint32_t a;
    asm("{ .reg .u64 t; cvta.to.shared.u64 t, %1; cvt.u32.u64 %0, t; }" : "=r"(a) : "l"(p));
    return a;
}
__device__ __forceinline__ void cpasync16(uint32_t dst, const void* src, int srcsize) {
    asm volatile("cp.async.cg.shared.global [%0], [%1], 16, %2;"
                 :: "r"(dst), "l"(src), "r"(srcsize) : "memory");
}
#define CP_COMMIT() asm volatile("cp.async.commit_group;" ::: "memory")
#define CP_WAIT1()  asm volatile("cp.async.wait_group 1;" ::: "memory")
#define CP_WAIT0()  asm volatile("cp.async.wait_group 0;" ::: "memory")

#define LDSM4(r, addr) \
    asm volatile("ldmatrix.sync.aligned.m8n8.x4.shared.b16 {%0,%1,%2,%3}, [%4];" \
                 : "=r"((r)[0]), "=r"((r)[1]), "=r"((r)[2]), "=r"((r)[3]) : "r"(addr))

#define MMA16816(d, a, b0_, b1_) \
    asm volatile("mma.sync.aligned.m16n8k16.row.col.f32.bf16.bf16.f32 " \
                 "{%0,%1,%2,%3}, {%4,%5,%6,%7}, {%8,%9}, {%0,%1,%2,%3};" \
                 : "+f"((d)[0]), "+f"((d)[1]), "+f"((d)[2]), "+f"((d)[3]) \
                 : "r"((a)[0]), "r"((a)[1]), "r"((a)[2]), "r"((a)[3]), "r"(b0_), "r"(b1_))

__device__ __forceinline__ uint32_t sw128(uint32_t off) {
    return off ^ ((off >> 3) & 0x70);
}

// ---------------- gathered GEMM via mma.sync, multi-descriptor dispatch ----------------
struct GDesc {
    const __nv_bfloat16* A;    // base, rows indexed by node*KP
    const __nv_bfloat16* B;    // [Nc, KP] K-major
    const float* bias;         // or null
    float* C;                  // rows = node - csub, ld = ldc
    const int* cnt;            // device list length
    const int* idx;            // node list
    int child4;                // A row r -> node 4*idx[r>>2]+1+(r&3)
    int sub;                   // node = idx[r] - sub (child4==0)
    int csub;
    int ldc;
    int Nc;
};
struct GDesc4 { GDesc d[4]; };

#define TILE_BYTES 16384
#define SMEM_TOTAL_MMA (4 * TILE_BYTES)

__global__ void __launch_bounds__(256, 1) gemm_multi(GDesc4 dd)
{
    const GDesc ds = dd.d[blockIdx.z];
    const int Nc = ds.Nc;
    const int col0 = blockIdx.x * 128;
    if (col0 >= Nc) return;
    const int nlist = *ds.cnt;
    const int Mrows = ds.child4 ? 4 * nlist : nlist;
    const int row0 = blockIdx.y * 128;
    if (row0 >= Mrows) return;

    extern __shared__ char smem[];
    const uint32_t sb = smem_u32(smem);
    const int tid  = threadIdx.x;
    const int wid  = tid >> 5;
    const int lane = tid & 31;
    const int wm   = wid & 3;
    const int wn   = wid >> 2;

    // cp.async mapping
    const int lrow = tid >> 1;
    const int lch0 = (tid & 1) * 4;
    const int g = row0 + lrow;
    int nodeA = 0, a_sz = 0;
    if (g < Mrows) {
        nodeA = ds.child4 ? (4 * ds.idx[g >> 2] + 1 + (g & 3)) : (ds.idx[g] - ds.sub);
        a_sz = 16;
    }
    const __nv_bfloat16* gA = ds.A + (size_t)nodeA * KP + lch0 * 8;
    const __nv_bfloat16* gB = ds.B + (size_t)(col0 + lrow) * KP + lch0 * 8;
    uint32_t sA[4], sB[4];
#pragma unroll
    for (int i = 0; i < 4; i++) {
        uint32_t off = sw128((uint32_t)(lrow * 128 + (lch0 + i) * 16));
        sA[i] = sb + off;
        sB[i] = sb + 2 * TILE_BYTES + off;
    }

    // ldmatrix offsets
    uint32_t offA[2][4], offB[4][4];
#pragma unroll
    for (int mi = 0; mi < 2; mi++)
#pragma unroll
        for (int kb = 0; kb < 4; kb++) {
            int r = wm * 32 + mi * 16 + (lane & 15);
            int k = kb * 16 + ((lane >> 4) << 3);
            offA[mi][kb] = sw128((uint32_t)(r * 128 + k * 2));
        }
#pragma unroll
    for (int ni = 0; ni < 4; ni++)
#pragma unroll
        for (int kb = 0; kb < 4; kb++) {
            int r = wn * 64 + ni * 16 + (lane & 7) + ((lane >> 4) << 3);
            int k = kb * 16 + (((lane >> 3) & 1) << 3);
            offB[ni][kb] = sw128((uint32_t)(r * 128 + k * 2));
        }

    float acc[2][8][4];
#pragma unroll
    for (int mi = 0; mi < 2; mi++)
#pragma unroll
        for (int nj = 0; nj < 8; nj++)
#pragma unroll
            for (int q = 0; q < 4; q++) acc[mi][nj][q] = 0.f;

#pragma unroll
    for (int i = 0; i < 4; i++) {
        cpasync16(sA[i], gA + i * 8, a_sz);
        cpasync16(sB[i], gB + i * 8, 16);
    }
    CP_COMMIT();

    for (int c = 0; c < NIT; c++) {
        if (c + 1 < NIT) {
            uint32_t bsel = ((c + 1) & 1) * TILE_BYTES;
            const __nv_bfloat16* pa = gA + (c + 1) * BKC;
            const __nv_bfloat16* pb = gB + (c + 1) * BKC;
#pragma unroll
            for (int i = 0; i < 4; i++) {
                cpasync16(sA[i] + bsel, pa + i * 8, a_sz);
                cpasync16(sB[i] + bsel, pb + i * 8, 16);
            }
            CP_COMMIT();
            CP_WAIT1();
        } else {
            CP_WAIT0();
        }
        __syncthreads();

        const uint32_t abase = sb + (c & 1) * TILE_BYTES;
        const uint32_t bbase = sb + 2 * TILE_BYTES + (c & 1) * TILE_BYTES;
#pragma unroll
        for (int kb = 0; kb < 4; kb++) {
            uint32_t a0[4], a1[4];
            LDSM4(a0, abase + offA[0][kb]);
            LDSM4(a1, abase + offA[1][kb]);
#pragma unroll
            for (int ni = 0; ni < 4; ni++) {
                uint32_t bt[4];
                LDSM4(bt, bbase + offB[ni][kb]);
                MMA16816(acc[0][2 * ni],     a0, bt[0], bt[1]);
                MMA16816(acc[0][2 * ni + 1], a0, bt[2], bt[3]);
                MMA16816(acc[1][2 * ni],     a1, bt[0], bt[1]);
                MMA16816(acc[1][2 * ni + 1], a1, bt[2], bt[3]);
            }
        }
        __syncthreads();
    }

    // epilogue (scatter rows through idx)
#pragma unroll
    for (int mi = 0; mi < 2; mi++) {
        int rbase = row0 + wm * 32 + mi * 16 + (lane >> 2);
#pragma unroll
        for (int half = 0; half < 2; half++) {
            int r = rbase + half * 8;
            if (r >= Mrows) continue;
            int node = ds.child4 ? (4 * ds.idx[r >> 2] + 1 + (r & 3)) : (ds.idx[r] - ds.sub);
            float* Crow = ds.C + (size_t)(node - ds.csub) * ds.ldc;
#pragma unroll
            for (int nj = 0; nj < 8; nj++) {
                int col = col0 + wn * 64 + nj * 8 + (lane & 3) * 2;
                float b0 = 0.f, b1 = 0.f;
                if (ds.bias) { b0 = ds.bias[col]; b1 = ds.bias[col + 1]; }
                float2 v = make_float2(acc[mi][nj][2 * half] + b0, acc[mi][nj][2 * half + 1] + b1);
                *(float2*)(Crow + col) = v;
            }
        }
    }
}

// ---------------- bf16 split ----------------
__device__ __forceinline__ void bsplit(float v, __nv_bfloat16& h, __nv_bfloat16& l) {
    h = __float2bfloat16(v);
    l = __float2bfloat16(v - __bfloat162float(h));
}

// ---------------- weight packing ----------------
// W-side triple layout: [hi | hi | lo]  (pairs with A-side [hi | lo | hi])
__global__ void pack_mod(const float* __restrict__ Wi_v, const float* __restrict__ Wi_l,
                         const float* __restrict__ Wf_v, const float* __restrict__ Wf_l,
                         const float* __restrict__ bi_v, const float* __restrict__ bi_l,
                         const float* __restrict__ bf_v, const float* __restrict__ bf_l)
{
    int idx = blockIdx.x * blockDim.x + threadIdx.x;   // m*131072 + kb*2048 + n
    if (idx >= 2 * 2048 * 64) return;
    int m  = idx >> 17;
    int rem = idx & 131071;
    int kb = rem >> 11;
    int n  = rem & 2047;
    const float* W; int col, ld;
    if (n < 1536) { W = m ? Wi_l : Wi_v; col = n;        ld = 1536; }
    else          { W = m ? Wf_l : Wf_v; col = n - 1536; ld = 512;  }
    __nv_bfloat16 hi8[8], lo8[8];
#pragma unroll
    for (int j = 0; j < 8; j++) bsplit(W[(size_t)(kb * 8 + j) * ld + col], hi8[j], lo8[j]);
    __nv_bfloat16* dst = g_Wmod[m];
    size_t b = (size_t)n * KP + kb * 8;
    *(uint4*)&dst[b]        = *(uint4*)hi8;
    *(uint4*)&dst[b + 512]  = *(uint4*)hi8;
    *(uint4*)&dst[b + 1024] = *(uint4*)lo8;
    if (kb == 0) {
        float bv;
        if (n < 1536) bv = m ? bi_l[n] : bi_v[n];
        else          bv = m ? bf_l[n - 1536] : bf_v[n - 1536];
        g_bmod[m][n] = bv;
    }
}

__global__ void pack_w(const float* __restrict__ Wv, const float* __restrict__ Wl,
                       __nv_bfloat16* __restrict__ dst, int rows)
{
    int idx = blockIdx.x * blockDim.x + threadIdx.x;   // m*rows*64 + kb*rows + n
    if (idx >= 2 * rows * 64) return;
    int m  = idx / (rows * 64);
    int rem = idx - m * rows * 64;
    int kb = rem / rows;
    int n  = rem - kb * rows;
    const float* W = m ? Wl : Wv;
    __nv_bfloat16 hi8[8], lo8[8];
#pragma unroll
    for (int j = 0; j < 8; j++) bsplit(W[(size_t)(kb * 8 + j) * rows + n], hi8[j], lo8[j]);
    size_t b = (size_t)m * rows * KP + (size_t)n * KP + kb * 8;
    *(uint4*)&dst[b]        = *(uint4*)hi8;
    *(uint4*)&dst[b + 512]  = *(uint4*)hi8;
    *(uint4*)&dst[b + 1024] = *(uint4*)lo8;
}

// ---------------- x split: [hi|lo|hi] ----------------
__global__ void split_x(const float* __restrict__ x)
{
    int idx = blockIdx.x * blockDim.x + threadIdx.x;
    if (idx >= NNODES * 64) return;
    int n = idx >> 6, kb = idx & 63;
    __nv_bfloat16 hi8[8], lo8[8];
    const float* p = x + (size_t)n * DIM + kb * 8;
#pragma unroll
    for (int j = 0; j < 8; j++) bsplit(p[j], hi8[j], lo8[j]);
    size_t b = (size_t)n * KP + kb * 8;
    *(uint4*)&g_xsplit[b]        = *(uint4*)hi8;
    *(uint4*)&g_xsplit[b + 512]  = *(uint4*)lo8;
    *(uint4*)&g_xsplit[b + 1024] = *(uint4*)hi8;
}

// ---------------- selection + grouping ----------------
__global__ void sel_kernel(const float* __restrict__ x,
                           const float* __restrict__ Wt,
                           const float* __restrict__ bt)
{
    int n = blockIdx.x * (blockDim.x >> 5) + (threadIdx.x >> 5);
    int lane = threadIdx.x & 31;
    if (n >= NNODES) return;
    float s0 = 0.f, s1 = 0.f;
    const float* xr = x + (size_t)n * DIM;
#pragma unroll 4
    for (int k = lane; k < DIM; k += 32) {
        float xv = xr[k];
        s0 = fmaf(xv, Wt[k * 2 + 0], s0);
        s1 = fmaf(xv, Wt[k * 2 + 1], s1);
    }
#pragma unroll
    for (int o = 16; o > 0; o >>= 1) {
        s0 += __shfl_xor_sync(0xFFFFFFFFu, s0, o);
        s1 += __shfl_xor_sync(0xFFFFFFFFu, s1, o);
    }
    if (lane == 0) g_sel[n] = (s0 + bt[0] >= s1 + bt[1]) ? 1 : 0;
}

__global__ void zero_cnt()
{
    int t = threadIdx.x;
    if (t < 2)  g_gcnt[t] = 0;
    if (t < 12) g_lcnt[t] = 0;
}

__global__ void group_kernel()
{
    const int STc[8] = {0, 1, 5, 21, 85, 341, 1365, 5461};
    int n = blockIdx.x * blockDim.x + threadIdx.x;
    if (n >= NNODES) return;
    int sl = g_sel[n];
    int pos = atomicAdd(&g_gcnt[sl], 1);
    g_gidx[sl * NNODES + pos] = n;
    if (n < NINT) {
        int l = 0;
        while (n >= STc[l + 1]) l++;
        int pos2 = atomicAdd(&g_lcnt[2 * l + sl], 1);
        int* arr = sl ? g_lidx_l : g_lidx_v;
        arr[STc[l] + pos2] = n;
    }
}

// ---------------- h write + split ----------------
__device__ __forceinline__ void write_h(int n, int j, float h, float* __restrict__ h_out) {
    h_out[(size_t)n * DIM + j] = h;
    __nv_bfloat16 hh, hl;
    bsplit(h, hh, hl);
    size_t b = (size_t)n * KP + j;
    g_hsplit[b]        = hh;
    g_hsplit[b + 512]  = hl;
    g_hsplit[b + 1024] = hh;
}

// ---------------- leaves ----------------
__global__ void leaf_kernel(const float* __restrict__ bi_v,
                            const float* __restrict__ bi_l,
                            float* __restrict__ h_out)
{
    int idx = blockIdx.x * blockDim.x + threadIdx.x;
    if (idx >= NLEAF * DIM) return;
    int n = LEAF_START + (idx >> 9);
    int j = idx & (DIM - 1);
    const float* bi = g_sel[n] ? bi_l : bi_v;
    size_t base = (size_t)n * 2048;
    float ig = g_pre[base + j]        + bi[j];
    float og = g_pre[base + 512 + j]  + bi[512 + j];
    float ug = g_pre[base + 1024 + j] + bi[1024 + j];
    float cc = sigmf(ig) * tanhf(ug);
    float hh = sigmf(og) * tanhf(cc);
    g_c[(size_t)n * DIM + j] = cc;
    write_h(n, j, hh, h_out);
}

// ---------------- h_sum + split (per level, compact index i) ----------------
__global__ void hsum_kernel(const float* __restrict__ h_all, int S1, int E)
{
    int idx = blockIdx.x * blockDim.x + threadIdx.x;
    if (idx >= E * DIM) return;
    int i = idx >> 9, j = idx & (DIM - 1);
    const float* b = h_all + (size_t)(S1 + 4 * i) * DIM + j;
    float s = (b[0] + b[DIM]) + (b[2 * DIM] + b[3 * DIM]);
    __nv_bfloat16 hh, hl;
    bsplit(s, hh, hl);
    size_t bb = (size_t)i * KP + j;
    g_hsumsplit[bb]        = hh;
    g_hsumsplit[bb + 512]  = hl;
    g_hsumsplit[bb + 1024] = hh;
}

// ---------------- internal-node gates ----------------
__global__ void gates_kernel(int s, int S1, int E,
                             const float* __restrict__ bi_v,
                             const float* __restrict__ bi_l,
                             const float* __restrict__ bf_v,
                             const float* __restrict__ bf_l,
                             float* __restrict__ h_out)
{
    int idx = blockIdx.x * blockDim.x + threadIdx.x;
    if (idx >= E * DIM) return;
    int i = idx >> 9, j = idx & (DIM - 1);
    int n = s + i;
    int sl = g_sel[n];
    const float* bi = sl ? bi_l : bi_v;
    const float* bf = sl ? bf_l : bf_v;
    size_t xb = (size_t)n * 2048;
    size_t hb = (size_t)i * 1536;
    float ig = g_pre[xb + j]        + g_hsiou[hb + j]        + bi[j];
    float og = g_pre[xb + 512 + j]  + g_hsiou[hb + 512 + j]  + bi[512 + j];
    float ug = g_pre[xb + 1024 + j] + g_hsiou[hb + 1024 + j] + bi[1024 + j];
    float fxv = g_pre[xb + 1536 + j] + bf[j];

    float cc = sigmf(ig) * tanhf(ug);
    size_t c0 = (size_t)(S1 + 4 * i) * DIM + j;
    size_t f0 = (size_t)(4 * i) * 512 + j;
#pragma unroll
    for (int k = 0; k < 4; k++) {
        float f = sigmf(g_fh[f0 + (size_t)k * 512] + fxv);
        cc = fmaf(f, g_c[c0 + (size_t)k * DIM], cc);
    }
    float hh = sigmf(og) * tanhf(cc);
    g_c[(size_t)n * DIM + j] = cc;
    write_h(n, j, hh, h_out);
}

// ---------------- launch ----------------
extern "C" void kernel_launch(void* const* d_in, const int* in_sizes, int n_in,
                              void* d_out, int out_size)
{
    const float* x        = (const float*)d_in[0];
    const float* W_ioux_v = (const float*)d_in[2];
    const float* b_ioux_v = (const float*)d_in[3];
    const float* W_iouh_v = (const float*)d_in[4];
    const float* b_iouh_v = (const float*)d_in[5];
    const float* W_fx_v   = (const float*)d_in[6];
    const float* b_fx_v   = (const float*)d_in[7];
    const float* W_fh_v   = (const float*)d_in[8];
    const float* b_fh_v   = (const float*)d_in[9];
    const float* W_ioux_l = (const float*)d_in[10];
    const float* b_ioux_l = (const float*)d_in[11];
    const float* W_iouh_l = (const float*)d_in[12];
    const float* b_iouh_l = (const float*)d_in[13];
    const float* W_fx_l   = (const float*)d_in[14];
    const float* b_fx_l   = (const float*)d_in[15];
    const float* W_fh_l   = (const float*)d_in[16];
    const float* b_fh_l   = (const float*)d_in[17];
    const float* W_type   = (const float*)d_in[18];
    const float* b_type   = (const float*)d_in[19];
    float* h_out = (float*)d_out;

    cudaFuncSetAttribute(gemm_multi, cudaFuncAttributeMaxDynamicSharedMemorySize, SMEM_TOTAL_MMA);

    __nv_bfloat16 *p_xsplit, *p_hsplit, *p_hsumsplit, *p_Wmod, *p_Wiouh, *p_Wfh;
    float *p_bmod, *p_pre, *p_hsiou, *p_fh;
    int *p_gcnt, *p_gidx, *p_lcnt, *p_lidx_v, *p_lidx_l;
    cudaGetSymbolAddress((void**)&p_xsplit,    g_xsplit);
    cudaGetSymbolAddress((void**)&p_hsplit,    g_hsplit);
    cudaGetSymbolAddress((void**)&p_hsumsplit, g_hsumsplit);
    cudaGetSymbolAddress((void**)&p_Wmod,      g_Wmod);
    cudaGetSymbolAddress((void**)&p_Wiouh,     g_Wiouh_m);
    cudaGetSymbolAddress((void**)&p_Wfh,       g_Wfh_m);
    cudaGetSymbolAddress((void**)&p_bmod,      g_bmod);
    cudaGetSymbolAddress((void**)&p_pre,       g_pre);
    cudaGetSymbolAddress((void**)&p_hsiou,     g_hsiou);
    cudaGetSymbolAddress((void**)&p_fh,        g_fh);
    cudaGetSymbolAddress((void**)&p_gcnt,      g_gcnt);
    cudaGetSymbolAddress((void**)&p_gidx,      g_gidx);
    cudaGetSymbolAddress((void**)&p_lcnt,      g_lcnt);
    cudaGetSymbolAddress((void**)&p_lidx_v,    g_lidx_v);
    cudaGetSymbolAddress((void**)&p_lidx_l,    g_lidx_l);

    // selection + grouping + packing + split
    sel_kernel<<<(NNODES + 7) / 8, 256>>>(x, W_type, b_type);
    zero_cnt<<<1, 32>>>();
    group_kernel<<<(NNODES + 255) / 256, 256>>>();
    pack_mod<<<(2 * 2048 * 64) / 256, 256>>>(W_ioux_v, W_ioux_l, W_fx_v, W_fx_l,
                                             b_ioux_v, b_ioux_l, b_fx_v, b_fx_l);
    pack_w<<<(2 * 1536 * 64) / 256, 256>>>(W_iouh_v, W_iouh_l, p_Wiouh, 1536);
    pack_w<<<(2 * 512 * 64) / 256, 256>>>(W_fh_v, W_fh_l, p_Wfh, 512);
    split_x<<<(NNODES * 64 + 255) / 256, 256>>>(x);

    // big precompute GEMM (selected modality only), z = modality
    {
        GDesc4 dd;
        for (int m = 0; m < 2; m++) {
            GDesc& d = dd.d[m];
            d.A = p_xsplit;
            d.B = p_Wmod + (size_t)m * 2048 * KP;
            d.bias = p_bmod + (size_t)m * 2048;
            d.C = p_pre;
            d.cnt = p_gcnt + m;
            d.idx = p_gidx + m * NNODES;
            d.child4 = 0; d.sub = 0; d.csub = 0; d.ldc = 2048; d.Nc = 2048;
        }
        dd.d[2] = dd.d[0]; dd.d[3] = dd.d[0];
        gemm_multi<<<dim3(16, 43, 2), 256, SMEM_TOTAL_MMA>>>(dd);
    }

    leaf_kernel<<<(NLEAF * DIM) / 256, 256>>>(b_ioux_v ? b_iouh_v : b_iouh_v, b_iouh_l, h_out);

    static const int ST[8] = {0, 1, 5, 21, 85, 341, 1365, 5461};
    for (int l = 5; l >= 0; --l) {
        int s  = ST[l];
        int S1 = ST[l + 1];
        int E  = ST[l + 1] - ST[l];
        hsum_kernel<<<(E * DIM + 255) / 256, 256>>>(h_out, S1, E);

        GDesc4 dd;
        for (int m = 0; m < 2; m++) {
            const int* lidx = (m ? p_lidx_l : p_lidx_v) + s;
            const int* lcnt = p_lcnt + 2 * l + m;
            // iouh: A = hsum (compact i = node - s), C = g_hsiou rows i
            GDesc& di = dd.d[2 * m];
            di.A = p_hsumsplit;
            di.B = p_Wiouh + (size_t)m * 1536 * KP;
            di.bias = nullptr;
            di.C = p_hsiou;
            di.cnt = lcnt; di.idx = lidx;
            di.child4 = 0; di.sub = s; di.csub = 0; di.ldc = 1536; di.Nc = 1536;
            // fh: A = hsplit rows = children, C = g_fh rows child - S1
            GDesc& df = dd.d[2 * m + 1];
            df.A = p_hsplit;
            df.B = p_Wfh + (size_t)m * 512 * KP;
            df.bias = nullptr;
            df.C = p_fh;
            df.cnt = lcnt; df.idx = lidx;
            df.child4 = 1; df.sub = 0; df.csub = S1; df.ldc = 512; df.Nc = 512;
        }
        int ytiles = (4 * E + 127) / 128;
        gemm_multi<<<dim3(12, ytiles, 4), 256, SMEM_TOTAL_MMA>>>(dd);

        gates_kernel<<<(E * DIM + 255) / 256, 256>>>(
            s, S1, E, b_iouh_v, b_iouh_l, b_fh_v, b_fh_l, h_out);
    }
}